// round 9
// baseline (speedup 1.0000x reference)
#include <cuda_runtime.h>
#include <math.h>

// MHGAttend: masked multi-head "attention" (reference bug: scores use V, not K).
// N=4096, HIDDEN=256, HEADS=8, Dh=32.
// 3-launch pipeline:
//   K1 qv_pack : q/v linears (head-major [H,N,Dh]) + ballot-coalesced Adj->bitmask.
//   K2 attn    : per (head, 64-row block): single-pass exp (no max subtraction,
//                fp32-safe; MUFU ex2.approx), FFMA2 (fma.rn.f32x2) inner loops
//                with pre-duplicated u64 q-tile (no pack movs in score loop).
//                Row sums accumulated inside the o-GEMM (no smem reduction).
//                Tail: normalize own attn stripe in place.
//   K3 wo      : final linear out_tmp@Wo^T+bo.

#define N_TOK  4096
#define HID    256
#define HEADS  8
#define DH     32
#define BM     64
#define BN     64
#define SP     (BM + 4)              // f32 tile row stride (68)
#define VP     (DH + 4)              // row-major v tile stride (36)
#define QP     (BM + 2)              // u64 q tile row stride (66)
#define MWORDS (N_TOK / 32)
// exp2 scale: log2(e)/sqrt(32)
#define SCALE_E ((float)(1.4426950408889634 / 5.656854249492381))

typedef unsigned long long u64;

// scratch (allocation-free rule: __device__ globals)
__device__ float    g_q[HEADS * N_TOK * DH];      // 4 MB
__device__ float    g_v[HEADS * N_TOK * DH];      // 4 MB
__device__ float    g_otmp[N_TOK * HID];          // 4 MB
__device__ unsigned g_mask[N_TOK * MWORDS];       // 2 MB

__device__ __forceinline__ float ex2f(float x) {
    float y;
    asm("ex2.approx.ftz.f32 %0, %1;" : "=f"(y) : "f"(x));
    return y;
}
// packed fp32x2 FMA: d = a*b + d
__device__ __forceinline__ void fma2(u64& d, u64 a, u64 b) {
    asm("fma.rn.f32x2 %0, %1, %2, %0;" : "+l"(d) : "l"(a), "l"(b));
}
__device__ __forceinline__ u64 pack2(float x) {
    u64 r;
    asm("mov.b64 %0, {%1, %1};" : "=l"(r) : "f"(x));
    return r;
}
__device__ __forceinline__ void unpack2(u64 v, float& lo, float& hi) {
    asm("mov.b64 {%0, %1}, %2;" : "=f"(lo), "=f"(hi) : "l"(v));
}

// ---------------------------------------------------------------- linear tile
// y = X @ W^T + b for one 64x64 output tile. Transposed smem tiles -> LDS.128.
__device__ __forceinline__ void linear_tile(
    const float* __restrict__ X, const float* __restrict__ W,
    const float* __restrict__ b, float* __restrict__ ext,
    int mode, int r0, int f0, int tid)
{
    __shared__ float xsT[32][SP];
    __shared__ float wsT[32][SP];
    int tx = tid & 15, ty = tid >> 4;
    float acc[4][4] = {};
    for (int kc = 0; kc < HID; kc += 32) {
        for (int i = tid; i < 64 * 8; i += 256) {
            int row = i >> 3, k4 = (i & 7) * 4;
            float4 tx4 = *reinterpret_cast<const float4*>(
                &X[(size_t)(r0 + row) * HID + kc + k4]);
            xsT[k4 + 0][row] = tx4.x; xsT[k4 + 1][row] = tx4.y;
            xsT[k4 + 2][row] = tx4.z; xsT[k4 + 3][row] = tx4.w;
            float4 tw4 = *reinterpret_cast<const float4*>(
                &W[(size_t)(f0 + row) * HID + kc + k4]);
            wsT[k4 + 0][row] = tw4.x; wsT[k4 + 1][row] = tw4.y;
            wsT[k4 + 2][row] = tw4.z; wsT[k4 + 3][row] = tw4.w;
        }
        __syncthreads();
#pragma unroll
        for (int k = 0; k < 32; k++) {
            float xv[4], wv[4];
            *reinterpret_cast<float4*>(xv) =
                *reinterpret_cast<const float4*>(&xsT[k][ty * 4]);
            *reinterpret_cast<float4*>(wv) =
                *reinterpret_cast<const float4*>(&wsT[k][tx * 4]);
#pragma unroll
            for (int i = 0; i < 4; i++)
#pragma unroll
                for (int j = 0; j < 4; j++) acc[i][j] += xv[i] * wv[j];
        }
        __syncthreads();
    }
    float* dstq = (mode == 0) ? g_q : g_v;
#pragma unroll
    for (int i = 0; i < 4; i++) {
        int n = r0 + ty * 4 + i;
#pragma unroll
        for (int j = 0; j < 4; j++) {
            int f = f0 + tx * 4 + j;
            float val = acc[i][j] + b[f];
            if (mode == 2)
                ext[(size_t)n * HID + f] = val;
            else
                dstq[(size_t)(f >> 5) * (N_TOK * DH) + (size_t)n * DH + (f & 31)] = val;
        }
    }
}

// ---------------------------------------------------------------- K1: qv + pack
// grid (96, 4, 2): x<64 -> linear tiles; x>=64 -> ballot-coalesced mask pack.
// Pack: 256 blocks * 8 warps = 2048 warps; each warp packs 256 words
// (8 rounds of 32 words). Round j: lane reads Adj[wbase*32 + j*32 + lane]
// (fully coalesced 128B), ballot -> word wbase+j, kept by lane==j.
__global__ __launch_bounds__(256) void qv_pack_kernel(
    const float* __restrict__ x,
    const float* __restrict__ wq_w, const float* __restrict__ wq_b,
    const float* __restrict__ wv_w, const float* __restrict__ wv_b,
    const int* __restrict__ Adj)
{
    const int tid = threadIdx.x;
    if (blockIdx.x < 64) {
        const int mode = blockIdx.z;
        linear_tile(x, mode == 0 ? wq_w : wv_w, mode == 0 ? wq_b : wv_b,
                    nullptr, mode, blockIdx.x * 64, blockIdx.y * 64, tid);
    } else {
        int pblk  = ((int)blockIdx.z * 4 + blockIdx.y) * 32 + (blockIdx.x - 64);
        int pwarp = pblk * 8 + (tid >> 5);          // 0..2047
        int lane  = tid & 31;
#pragma unroll
        for (int s = 0; s < 8; s++) {
            int wbase = pwarp * 256 + s * 32;
            const int* base = Adj + (size_t)wbase * 32;
            unsigned my = 0;
#pragma unroll
            for (int j = 0; j < 32; j++) {
                int v = base[j * 32 + lane];
                unsigned bal = __ballot_sync(0xffffffffu, v != 0);
                if (j == lane) my = bal;
            }
            g_mask[wbase + lane] = my;
        }
    }
}

// ---------------------------------------------------------------- K2: attention
__global__ __launch_bounds__(256) void attn_kernel(float* __restrict__ attn_out,
                                                   int write_attn)
{
    const int h = blockIdx.y;
    const int r0 = blockIdx.x * BM;
    const float* qh = g_q + (size_t)h * N_TOK * DH;
    const float* vh = g_v + (size_t)h * N_TOK * DH;

    __shared__ u64   qs2[DH][QP];        // [k][row] pre-duplicated {q,q}, pre-scaled  (16.9KB)
    __shared__ float vsT[DH][SP];        // [k][col]   score GEMM                      (8.7KB)
    __shared__ float vs[BN][VP];         // [col][k]   o GEMM                          (9.2KB)
    __shared__ float ps[BM][SP];         // p tile                                     (17.4KB)
    __shared__ float l_s[BM];

    const int tid = threadIdx.x, tx = tid & 15, ty = tid >> 4;

    // q tile: load float4, scale, duplicate into u64 pairs
    for (int i = tid; i < BM * DH / 4; i += 256) {
        int row = i >> 3;
        int k4  = (i & 7) * 4;
        float4 t4 = *reinterpret_cast<const float4*>(&qh[(size_t)(r0 + row) * DH + k4]);
        qs2[k4 + 0][row] = pack2(t4.x * SCALE_E);
        qs2[k4 + 1][row] = pack2(t4.y * SCALE_E);
        qs2[k4 + 2][row] = pack2(t4.z * SCALE_E);
        qs2[k4 + 3][row] = pack2(t4.w * SCALE_E);
    }
    __syncthreads();

    u64 o2[4] = {0ull, 0ull, 0ull, 0ull};      // 8 packed fp32 out accumulators
    float l_acc = 0.f;                         // row sum (od0==0 threads only)
    const int orow = tid >> 2;                 // 0..63
    const int od0  = (tid & 3) * 8;            // 0/8/16/24

    for (int jt = 0; jt < N_TOK / BN; jt++) {
        const int c0 = jt * BN;
        __syncthreads();                       // protect vs/vsT reuse
        for (int i = tid; i < BN * DH / 4; i += 256) {
            int row = i >> 3;
            int k4  = (i & 7) * 4;
            float4 t4 = *reinterpret_cast<const float4*>(&vh[(size_t)(c0 + row) * DH + k4]);
            *reinterpret_cast<float4*>(&vs[row][k4]) = t4;
            vsT[k4 + 0][row] = t4.x; vsT[k4 + 1][row] = t4.y;
            vsT[k4 + 2][row] = t4.z; vsT[k4 + 3][row] = t4.w;
        }
        __syncthreads();

        // scores: 3 LDS.128 + 8 FFMA2 per k (no pack movs)
        u64 s2[4][2] = {};
#pragma unroll
        for (int k = 0; k < DH; k++) {
            ulonglong2 qa = *reinterpret_cast<const ulonglong2*>(&qs2[k][ty * 4]);
            ulonglong2 qb = *reinterpret_cast<const ulonglong2*>(&qs2[k][ty * 4 + 2]);
            ulonglong2 vv = *reinterpret_cast<const ulonglong2*>(&vsT[k][tx * 4]);
            fma2(s2[0][0], qa.x, vv.x); fma2(s2[0][1], qa.x, vv.y);
            fma2(s2[1][0], qa.y, vv.x); fma2(s2[1][1], qa.y, vv.y);
            fma2(s2[2][0], qb.x, vv.x); fma2(s2[2][1], qb.x, vv.y);
            fma2(s2[3][0], qb.y, vv.x); fma2(s2[3][1], qb.y, vv.y);
        }

        // mask + exp (unnormalized); write global + smem p tile
#pragma unroll
        for (int i = 0; i < 4; i++) {
            const int r = ty * 4 + i;
            unsigned w = g_mask[(size_t)(r0 + r) * MWORDS + ((c0 + tx * 4) >> 5)];
            float s[4];
            unpack2(s2[i][0], s[0], s[1]);
            unpack2(s2[i][1], s[2], s[3]);
            float p[4];
#pragma unroll
            for (int j = 0; j < 4; j++) {
                int bit = (tx * 4 + j) & 31;
                p[j] = ((w >> bit) & 1u) ? ex2f(s[j]) : 0.f;
            }
            *reinterpret_cast<float4*>(&ps[r][tx * 4]) =
                make_float4(p[0], p[1], p[2], p[3]);
            if (write_attn) {
                *reinterpret_cast<float4*>(
                    &attn_out[((size_t)(h * N_TOK) + r0 + r) * N_TOK + c0 + tx * 4])
                    = make_float4(p[0], p[1], p[2], p[3]);
            }
        }
        __syncthreads();

        // o += p_tile @ v_tile; od0==0 threads also accumulate row sum l
#pragma unroll
        for (int c4 = 0; c4 < BN; c4 += 4) {
            float a[4];
            *reinterpret_cast<float4*>(a) =
                *reinterpret_cast<const float4*>(&ps[orow][c4]);
            if ((tid & 3) == 0)
                l_acc += (a[0] + a[1]) + (a[2] + a[3]);
#pragma unroll
            for (int u = 0; u < 4; u++) {
                ulonglong2 v0 = *reinterpret_cast<const ulonglong2*>(&vs[c4 + u][od0]);
                ulonglong2 v1 = *reinterpret_cast<const ulonglong2*>(&vs[c4 + u][od0 + 4]);
                u64 a2 = pack2(a[u]);
                fma2(o2[0], a2, v0.x);
                fma2(o2[1], a2, v0.y);
                fma2(o2[2], a2, v1.x);
                fma2(o2[3], a2, v1.y);
            }
        }
    }

    // finalize l -> 1/l
    if ((tid & 3) == 0) l_s[orow] = l_acc;
    __syncthreads();
    if (tid < BM) l_s[tid] = 1.0f / l_s[tid];
    __syncthreads();

    // o epilogue (normalized, float4 stores)
    {
        const float li = l_s[orow];
        float o[8];
        unpack2(o2[0], o[0], o[1]);
        unpack2(o2[1], o[2], o[3]);
        unpack2(o2[2], o[4], o[5]);
        unpack2(o2[3], o[6], o[7]);
#pragma unroll
        for (int j = 0; j < 8; j++) o[j] *= li;
        float* dst = &g_otmp[(size_t)(r0 + orow) * HID + h * DH + od0];
        *reinterpret_cast<float4*>(dst)     = make_float4(o[0], o[1], o[2], o[3]);
        *reinterpret_cast<float4*>(dst + 4) = make_float4(o[4], o[5], o[6], o[7]);
    }

    // normalize own attn stripe in place (block-local; visible post-barrier)
    if (write_attn) {
        float4* base = reinterpret_cast<float4*>(
            attn_out + ((size_t)(h * N_TOK) + r0) * N_TOK);
        for (int i = tid; i < BM * (N_TOK / 4); i += 256) {
            const float li = l_s[i >> 10];          // 1024 float4 per row
            float4 v = base[i];
            v.x *= li; v.y *= li; v.z *= li; v.w *= li;
            base[i] = v;
        }
    }
}

// ---------------------------------------------------------------- K3: wo linear
__global__ __launch_bounds__(256) void wo_kernel(
    float* __restrict__ out,
    const float* __restrict__ wo_w, const float* __restrict__ wo_b)
{
    linear_tile(g_otmp, wo_w, wo_b, out, 2,
                (blockIdx.x >> 2) * 64, (blockIdx.x & 3) * 64, threadIdx.x);
}

// ---------------------------------------------------------------- launch
extern "C" void kernel_launch(void* const* d_in, const int* in_sizes, int n_in,
                              void* d_out, int out_size)
{
    const float* x    = (const float*)d_in[0];
    const int*   Adj  = (const int*)  d_in[1];
    const float* wq_w = (const float*)d_in[2];
    const float* wq_b = (const float*)d_in[3];
    // d_in[4], d_in[5] = wk (dead in reference: scores use V)
    const float* wv_w = (const float*)d_in[6];
    const float* wv_b = (const float*)d_in[7];
    const float* wo_w = (const float*)d_in[8];
    const float* wo_b = (const float*)d_in[9];
    float* out = (float*)d_out;

    const long long need = (long long)N_TOK * HID + (long long)HEADS * N_TOK * N_TOK;
    int write_attn = ((long long)out_size >= need) ? 1 : 0;
    float* attn_out = out + (size_t)N_TOK * HID;

    qv_pack_kernel<<<dim3(96, 4, 2), 256>>>(x, wq_w, wq_b, wv_w, wv_b, Adj);
    attn_kernel<<<dim3(N_TOK / BM, HEADS), 256>>>(attn_out, write_attn);
    wo_kernel<<<256, 256>>>(out, wo_w, wo_b);
}

// round 11
// speedup vs baseline: 1.4582x; 1.4582x over previous
#include <cuda_runtime.h>
#include <math.h>

// MHGAttend: masked multi-head "attention" (reference bug: scores use V, not K).
// N=4096, HIDDEN=256, HEADS=8, Dh=32.
// 4-launch pipeline (attn split in two so ncu -s5 lands on it):
//   K1 qv_pack : q/v linears (head-major [H,N,Dh]) + ballot-coalesced Adj->bitmask.
//   K2a/K2b    : attention over heads 0-3 / 4-7. Per (head, 64-row block):
//                single-pass exp (no max subtraction, fp32-safe; MUFU ex2),
//                scalar-FFMA 4x4 register tiles, double-buffered v tiles with
//                LDG prefetch overlapped with compute, mask words prefetched
//                under the score GEMM. Unnormalized p written to attn, l
//                accumulated inside the o-GEMM, own stripe normalized in place.
//   K3 wo      : final linear out_tmp@Wo^T+bo.

#define N_TOK  4096
#define HID    256
#define HEADS  8
#define DH     32
#define BM     64
#define BN     64
#define SP     (BM + 4)              // f32 tile row stride (68)
#define VP     (DH + 4)              // row-major v tile stride (36)
#define MWORDS (N_TOK / 32)
// exp2 scale: log2(e)/sqrt(32)
#define SCALE_E ((float)(1.4426950408889634 / 5.656854249492381))

// scratch (allocation-free rule: __device__ globals)
__device__ float    g_q[HEADS * N_TOK * DH];      // 4 MB
__device__ float    g_v[HEADS * N_TOK * DH];      // 4 MB
__device__ float    g_otmp[N_TOK * HID];          // 4 MB
__device__ unsigned g_mask[N_TOK * MWORDS];       // 2 MB

__device__ __forceinline__ float ex2f(float x) {
    float y;
    asm("ex2.approx.ftz.f32 %0, %1;" : "=f"(y) : "f"(x));
    return y;
}

// ---------------------------------------------------------------- linear tile
// y = X @ W^T + b for one 64x64 output tile. Transposed smem tiles -> LDS.128.
__device__ __forceinline__ void linear_tile(
    const float* __restrict__ X, const float* __restrict__ W,
    const float* __restrict__ b, float* __restrict__ ext,
    int mode, int r0, int f0, int tid)
{
    __shared__ float xsT[32][SP];
    __shared__ float wsT[32][SP];
    int tx = tid & 15, ty = tid >> 4;
    float acc[4][4] = {};
    for (int kc = 0; kc < HID; kc += 32) {
        for (int i = tid; i < 64 * 8; i += 256) {
            int row = i >> 3, k4 = (i & 7) * 4;
            float4 tx4 = *reinterpret_cast<const float4*>(
                &X[(size_t)(r0 + row) * HID + kc + k4]);
            xsT[k4 + 0][row] = tx4.x; xsT[k4 + 1][row] = tx4.y;
            xsT[k4 + 2][row] = tx4.z; xsT[k4 + 3][row] = tx4.w;
            float4 tw4 = *reinterpret_cast<const float4*>(
                &W[(size_t)(f0 + row) * HID + kc + k4]);
            wsT[k4 + 0][row] = tw4.x; wsT[k4 + 1][row] = tw4.y;
            wsT[k4 + 2][row] = tw4.z; wsT[k4 + 3][row] = tw4.w;
        }
        __syncthreads();
#pragma unroll
        for (int k = 0; k < 32; k++) {
            float xv[4], wv[4];
            *reinterpret_cast<float4*>(xv) =
                *reinterpret_cast<const float4*>(&xsT[k][ty * 4]);
            *reinterpret_cast<float4*>(wv) =
                *reinterpret_cast<const float4*>(&wsT[k][tx * 4]);
#pragma unroll
            for (int i = 0; i < 4; i++)
#pragma unroll
                for (int j = 0; j < 4; j++) acc[i][j] += xv[i] * wv[j];
        }
        __syncthreads();
    }
    float* dstq = (mode == 0) ? g_q : g_v;
#pragma unroll
    for (int i = 0; i < 4; i++) {
        int n = r0 + ty * 4 + i;
#pragma unroll
        for (int j = 0; j < 4; j++) {
            int f = f0 + tx * 4 + j;
            float val = acc[i][j] + b[f];
            if (mode == 2)
                ext[(size_t)n * HID + f] = val;
            else
                dstq[(size_t)(f >> 5) * (N_TOK * DH) + (size_t)n * DH + (f & 31)] = val;
        }
    }
}

// ---------------------------------------------------------------- K1: qv + pack
__global__ __launch_bounds__(256) void qv_pack_kernel(
    const float* __restrict__ x,
    const float* __restrict__ wq_w, const float* __restrict__ wq_b,
    const float* __restrict__ wv_w, const float* __restrict__ wv_b,
    const int* __restrict__ Adj)
{
    const int tid = threadIdx.x;
    if (blockIdx.x < 64) {
        const int mode = blockIdx.z;
        linear_tile(x, mode == 0 ? wq_w : wv_w, mode == 0 ? wq_b : wv_b,
                    nullptr, mode, blockIdx.x * 64, blockIdx.y * 64, tid);
    } else {
        int pblk  = ((int)blockIdx.z * 4 + blockIdx.y) * 32 + (blockIdx.x - 64);
        int pwarp = pblk * 8 + (tid >> 5);          // 0..2047
        int lane  = tid & 31;
#pragma unroll
        for (int s = 0; s < 8; s++) {
            int wbase = pwarp * 256 + s * 32;
            const int* base = Adj + (size_t)wbase * 32;
            unsigned my = 0;
#pragma unroll
            for (int j = 0; j < 32; j++) {
                int v = base[j * 32 + lane];
                unsigned bal = __ballot_sync(0xffffffffu, v != 0);
                if (j == lane) my = bal;
            }
            g_mask[wbase + lane] = my;
        }
    }
}

// ---------------------------------------------------------------- K2: attention
// h = blockIdx.y + h0 (4 heads per launch). Double-buffered v tiles; LDG
// prefetch of tile jt+1 and the 4 mask words both issued before the score
// GEMM so their latency hides under ~2000 cycles of FFMA.
__global__ __launch_bounds__(256) void attn_kernel(float* __restrict__ attn_out,
                                                   int write_attn, int h0)
{
    const int h = blockIdx.y + h0;
    const int r0 = blockIdx.x * BM;
    const float* qh = g_q + (size_t)h * N_TOK * DH;
    const float* vh = g_v + (size_t)h * N_TOK * DH;

    __shared__ float qsT[DH][SP];        // [k][row]   score GEMM  (8.7 KB)
    __shared__ float vsT[2][DH][SP];     // [k][col]   score GEMM  (17.4 KB)
    __shared__ float vs[2][BN][VP];      // [col][k]   o GEMM      (18.4 KB)
    __shared__ float ps[BM][SP];         // p tile                 (17.4 KB)
    __shared__ float l_s[BM];

    const int tid = threadIdx.x, tx = tid & 15, ty = tid >> 4;
    const int vrow = tid >> 3;            // 0..31 (thread's 2 v rows: vrow, vrow+32)
    const int vk4  = (tid & 7) * 4;

    // q tile: transposed, pre-scaled
    for (int i = tid; i < BM * DH / 4; i += 256) {
        int row = i >> 3, k4 = (i & 7) * 4;
        float4 t4 = *reinterpret_cast<const float4*>(&qh[(size_t)(r0 + row) * DH + k4]);
        qsT[k4 + 0][row] = t4.x * SCALE_E; qsT[k4 + 1][row] = t4.y * SCALE_E;
        qsT[k4 + 2][row] = t4.z * SCALE_E; qsT[k4 + 3][row] = t4.w * SCALE_E;
    }

    // prefetch + store v tile 0 into buffer 0
    float4 pf0 = *reinterpret_cast<const float4*>(&vh[(size_t)vrow * DH + vk4]);
    float4 pf1 = *reinterpret_cast<const float4*>(&vh[(size_t)(vrow + 32) * DH + vk4]);
    *reinterpret_cast<float4*>(&vs[0][vrow][vk4]) = pf0;
    *reinterpret_cast<float4*>(&vs[0][vrow + 32][vk4]) = pf1;
    vsT[0][vk4 + 0][vrow] = pf0.x; vsT[0][vk4 + 1][vrow] = pf0.y;
    vsT[0][vk4 + 2][vrow] = pf0.z; vsT[0][vk4 + 3][vrow] = pf0.w;
    vsT[0][vk4 + 0][vrow + 32] = pf1.x; vsT[0][vk4 + 1][vrow + 32] = pf1.y;
    vsT[0][vk4 + 2][vrow + 32] = pf1.z; vsT[0][vk4 + 3][vrow + 32] = pf1.w;
    __syncthreads();

    float o[8] = {};
    float l_acc = 0.f;                   // row sum (tid&3==0 threads)
    const int orow = tid >> 2;           // 0..63
    const int od0  = (tid & 3) * 8;      // 0/8/16/24

    for (int jt = 0; jt < N_TOK / BN; jt++) {
        const int c0 = jt * BN;
        const int cur = jt & 1, nxt = cur ^ 1;

        // prefetch next v tile (global -> regs), hidden under score compute
        if (jt < N_TOK / BN - 1) {
            const float* vn = vh + (size_t)(c0 + BN) * DH;
            pf0 = *reinterpret_cast<const float4*>(&vn[(size_t)vrow * DH + vk4]);
            pf1 = *reinterpret_cast<const float4*>(&vn[(size_t)(vrow + 32) * DH + vk4]);
        }
        // prefetch this tile's 4 mask words (L2-hit latency hides under FFMA)
        unsigned wmask[4];
        {
            const int mcol = (c0 + tx * 4) >> 5;
#pragma unroll
            for (int i = 0; i < 4; i++)
                wmask[i] = g_mask[(size_t)(r0 + ty * 4 + i) * MWORDS + mcol];
        }

        // scores: s[i][j] = (q*c)[r0+ty*4+i] . v[c0+tx*4+j]
        float s[4][4] = {};
#pragma unroll
        for (int k = 0; k < DH; k++) {
            float qv[4], vv[4];
            *reinterpret_cast<float4*>(qv) =
                *reinterpret_cast<const float4*>(&qsT[k][ty * 4]);
            *reinterpret_cast<float4*>(vv) =
                *reinterpret_cast<const float4*>(&vsT[cur][k][tx * 4]);
#pragma unroll
            for (int i = 0; i < 4; i++)
#pragma unroll
                for (int j = 0; j < 4; j++) s[i][j] += qv[i] * vv[j];
        }

        // mask + exp (unnormalized); write smem ps + global attn
#pragma unroll
        for (int i = 0; i < 4; i++) {
            const int r = ty * 4 + i;
            float p[4];
#pragma unroll
            for (int j = 0; j < 4; j++) {
                int bit = (tx * 4 + j) & 31;
                p[j] = ((wmask[i] >> bit) & 1u) ? ex2f(s[i][j]) : 0.f;
            }
            *reinterpret_cast<float4*>(&ps[r][tx * 4]) =
                make_float4(p[0], p[1], p[2], p[3]);
            if (write_attn) {
                *reinterpret_cast<float4*>(
                    &attn_out[((size_t)(h * N_TOK) + r0 + r) * N_TOK + c0 + tx * 4])
                    = make_float4(p[0], p[1], p[2], p[3]);
            }
        }
        __syncthreads();   // ps ready; all reads of buffer nxt (tile jt-1) done

        // store prefetched v tile into the other buffer (overlaps o-GEMM issue)
        if (jt < N_TOK / BN - 1) {
            *reinterpret_cast<float4*>(&vs[nxt][vrow][vk4]) = pf0;
            *reinterpret_cast<float4*>(&vs[nxt][vrow + 32][vk4]) = pf1;
            vsT[nxt][vk4 + 0][vrow] = pf0.x; vsT[nxt][vk4 + 1][vrow] = pf0.y;
            vsT[nxt][vk4 + 2][vrow] = pf0.z; vsT[nxt][vk4 + 3][vrow] = pf0.w;
            vsT[nxt][vk4 + 0][vrow + 32] = pf1.x; vsT[nxt][vk4 + 1][vrow + 32] = pf1.y;
            vsT[nxt][vk4 + 2][vrow + 32] = pf1.z; vsT[nxt][vk4 + 3][vrow + 32] = pf1.w;
        }

        // o += p_tile @ v_tile; tid&3==0 threads accumulate row sum l
#pragma unroll
        for (int c4 = 0; c4 < BN; c4 += 4) {
            float a[4];
            *reinterpret_cast<float4*>(a) =
                *reinterpret_cast<const float4*>(&ps[orow][c4]);
            if ((tid & 3) == 0)
                l_acc += (a[0] + a[1]) + (a[2] + a[3]);
#pragma unroll
            for (int u = 0; u < 4; u++) {
                float vv[8];
                *reinterpret_cast<float4*>(vv) =
                    *reinterpret_cast<const float4*>(&vs[cur][c4 + u][od0]);
                *reinterpret_cast<float4*>(vv + 4) =
                    *reinterpret_cast<const float4*>(&vs[cur][c4 + u][od0 + 4]);
#pragma unroll
                for (int j = 0; j < 8; j++) o[j] += a[u] * vv[j];
            }
        }
        __syncthreads();   // o-GEMM done with ps; buffer nxt fully written
    }

    // finalize l -> 1/l
    if ((tid & 3) == 0) l_s[orow] = l_acc;
    __syncthreads();
    if (tid < BM) l_s[tid] = 1.0f / l_s[tid];
    __syncthreads();

    // o epilogue (normalized, float4 stores)
    {
        const float li = l_s[orow];
#pragma unroll
        for (int j = 0; j < 8; j++) o[j] *= li;
        float* dst = &g_otmp[(size_t)(r0 + orow) * HID + h * DH + od0];
        *reinterpret_cast<float4*>(dst)     = make_float4(o[0], o[1], o[2], o[3]);
        *reinterpret_cast<float4*>(dst + 4) = make_float4(o[4], o[5], o[6], o[7]);
    }

    // normalize own attn stripe in place (block-local; visible post-barrier)
    if (write_attn) {
        float4* base = reinterpret_cast<float4*>(
            attn_out + ((size_t)(h * N_TOK) + r0) * N_TOK);
        for (int i = tid; i < BM * (N_TOK / 4); i += 256) {
            const float li = l_s[i >> 10];          // 1024 float4 per row
            float4 v = base[i];
            v.x *= li; v.y *= li; v.z *= li; v.w *= li;
            base[i] = v;
        }
    }
}

// ---------------------------------------------------------------- K3: wo linear
__global__ __launch_bounds__(256) void wo_kernel(
    float* __restrict__ out,
    const float* __restrict__ wo_w, const float* __restrict__ wo_b)
{
    linear_tile(g_otmp, wo_w, wo_b, out, 2,
                (blockIdx.x >> 2) * 64, (blockIdx.x & 3) * 64, threadIdx.x);
}

// ---------------------------------------------------------------- launch
extern "C" void kernel_launch(void* const* d_in, const int* in_sizes, int n_in,
                              void* d_out, int out_size)
{
    const float* x    = (const float*)d_in[0];
    const int*   Adj  = (const int*)  d_in[1];
    const float* wq_w = (const float*)d_in[2];
    const float* wq_b = (const float*)d_in[3];
    // d_in[4], d_in[5] = wk (dead in reference: scores use V)
    const float* wv_w = (const float*)d_in[6];
    const float* wv_b = (const float*)d_in[7];
    const float* wo_w = (const float*)d_in[8];
    const float* wo_b = (const float*)d_in[9];
    float* out = (float*)d_out;

    const long long need = (long long)N_TOK * HID + (long long)HEADS * N_TOK * N_TOK;
    int write_attn = ((long long)out_size >= need) ? 1 : 0;
    float* attn_out = out + (size_t)N_TOK * HID;

    qv_pack_kernel<<<dim3(96, 4, 2), 256>>>(x, wq_w, wq_b, wv_w, wv_b, Adj);
    // attn split into two launches so the ncu capture window (-s 5 -c 1)
    // lands on an attention launch regardless of alignment
    attn_kernel<<<dim3(N_TOK / BM, 4), 256>>>(attn_out, write_attn, 0);
    attn_kernel<<<dim3(N_TOK / BM, 4), 256>>>(attn_out, write_attn, 4);
    wo_kernel<<<256, 256>>>(out, wo_w, wo_b);
}

// round 13
// speedup vs baseline: 1.5437x; 1.0587x over previous
#include <cuda_runtime.h>
#include <math.h>

// MHGAttend: masked multi-head "attention" (reference bug: scores use V, not K).
// N=4096, HIDDEN=256, HEADS=8, Dh=32.
// 5-launch pipeline: K1 qv+pack, K2a attn units 0-67, shim, K2b attn units
// 68-511 (444 blocks = exactly 3/SM x 148 -> one balanced wave; also puts the
// big attn launch at capture index 3 so ncu -s5 finally profiles it), K3 wo.

#define N_TOK  4096
#define HID    256
#define HEADS  8
#define DH     32
#define BM     64
#define BN     64
#define SP     (BM + 4)              // f32 tile row stride (68)
#define VP     (DH + 4)              // row-major v tile stride (36)
#define MWORDS (N_TOK / 32)
// exp2 scale: log2(e)/sqrt(32)
#define SCALE_E ((float)(1.4426950408889634 / 5.656854249492381))

// scratch (allocation-free rule: __device__ globals)
__device__ float    g_q[HEADS * N_TOK * DH];      // 4 MB
__device__ float    g_v[HEADS * N_TOK * DH];      // 4 MB
__device__ float    g_otmp[N_TOK * HID];          // 4 MB
__device__ unsigned g_mask[N_TOK * MWORDS];       // 2 MB

__device__ __forceinline__ float ex2f(float x) {
    float y;
    asm("ex2.approx.ftz.f32 %0, %1;" : "=f"(y) : "f"(x));
    return y;
}

// ---------------------------------------------------------------- linear tile
// y = X @ W^T + b for one 64x64 output tile. Transposed smem tiles -> LDS.128.
__device__ __forceinline__ void linear_tile(
    const float* __restrict__ X, const float* __restrict__ W,
    const float* __restrict__ b, float* __restrict__ ext,
    int mode, int r0, int f0, int tid)
{
    __shared__ float xsT[32][SP];
    __shared__ float wsT[32][SP];
    int tx = tid & 15, ty = tid >> 4;
    float acc[4][4] = {};
    for (int kc = 0; kc < HID; kc += 32) {
        for (int i = tid; i < 64 * 8; i += 256) {
            int row = i >> 3, k4 = (i & 7) * 4;
            float4 tx4 = *reinterpret_cast<const float4*>(
                &X[(size_t)(r0 + row) * HID + kc + k4]);
            xsT[k4 + 0][row] = tx4.x; xsT[k4 + 1][row] = tx4.y;
            xsT[k4 + 2][row] = tx4.z; xsT[k4 + 3][row] = tx4.w;
            float4 tw4 = *reinterpret_cast<const float4*>(
                &W[(size_t)(f0 + row) * HID + kc + k4]);
            wsT[k4 + 0][row] = tw4.x; wsT[k4 + 1][row] = tw4.y;
            wsT[k4 + 2][row] = tw4.z; wsT[k4 + 3][row] = tw4.w;
        }
        __syncthreads();
#pragma unroll
        for (int k = 0; k < 32; k++) {
            float xv[4], wv[4];
            *reinterpret_cast<float4*>(xv) =
                *reinterpret_cast<const float4*>(&xsT[k][ty * 4]);
            *reinterpret_cast<float4*>(wv) =
                *reinterpret_cast<const float4*>(&wsT[k][tx * 4]);
#pragma unroll
            for (int i = 0; i < 4; i++)
#pragma unroll
                for (int j = 0; j < 4; j++) acc[i][j] += xv[i] * wv[j];
        }
        __syncthreads();
    }
    float* dstq = (mode == 0) ? g_q : g_v;
#pragma unroll
    for (int i = 0; i < 4; i++) {
        int n = r0 + ty * 4 + i;
#pragma unroll
        for (int j = 0; j < 4; j++) {
            int f = f0 + tx * 4 + j;
            float val = acc[i][j] + b[f];
            if (mode == 2)
                ext[(size_t)n * HID + f] = val;
            else
                dstq[(size_t)(f >> 5) * (N_TOK * DH) + (size_t)n * DH + (f & 31)] = val;
        }
    }
}

// ---------------------------------------------------------------- K1: qv + pack
__global__ __launch_bounds__(256) void qv_pack_kernel(
    const float* __restrict__ x,
    const float* __restrict__ wq_w, const float* __restrict__ wq_b,
    const float* __restrict__ wv_w, const float* __restrict__ wv_b,
    const int* __restrict__ Adj)
{
    const int tid = threadIdx.x;
    if (blockIdx.x < 64) {
        const int mode = blockIdx.z;
        linear_tile(x, mode == 0 ? wq_w : wv_w, mode == 0 ? wq_b : wv_b,
                    nullptr, mode, blockIdx.x * 64, blockIdx.y * 64, tid);
    } else {
        int pblk  = ((int)blockIdx.z * 4 + blockIdx.y) * 32 + (blockIdx.x - 64);
        int pwarp = pblk * 8 + (tid >> 5);          // 0..2047
        int lane  = tid & 31;
#pragma unroll
        for (int s = 0; s < 8; s++) {
            int wbase = pwarp * 256 + s * 32;
            const int* base = Adj + (size_t)wbase * 32;
            unsigned my = 0;
#pragma unroll
            for (int j = 0; j < 32; j++) {
                int v = base[j * 32 + lane];
                unsigned bal = __ballot_sync(0xffffffffu, v != 0);
                if (j == lane) my = bal;
            }
            g_mask[wbase + lane] = my;
        }
    }
}

// ---------------------------------------------------------------- K2: attention
// unit = unit0 + blockIdx.x in 0..511; h = unit>>6, r0 = (unit&63)*64.
// Double-buffered v tiles; LDG prefetch of tile jt+1 and the 4 mask words
// issued before the score GEMM so their latency hides under the FFMA block.
__global__ __launch_bounds__(256) void attn_kernel(float* __restrict__ attn_out,
                                                   int write_attn, int unit0)
{
    const int unit = unit0 + blockIdx.x;
    const int h  = unit >> 6;
    const int r0 = (unit & 63) * BM;
    const float* qh = g_q + (size_t)h * N_TOK * DH;
    const float* vh = g_v + (size_t)h * N_TOK * DH;

    __shared__ float qsT[DH][SP];        // [k][row]   score GEMM  (8.7 KB)
    __shared__ float vsT[2][DH][SP];     // [k][col]   score GEMM  (17.4 KB)
    __shared__ float vs[2][BN][VP];      // [col][k]   o GEMM      (18.4 KB)
    __shared__ float ps[BM][SP];         // p tile                 (17.4 KB)
    __shared__ float l_s[BM];

    const int tid = threadIdx.x, tx = tid & 15, ty = tid >> 4;
    const int vrow = tid >> 3;            // 0..31 (thread's 2 v rows: vrow, vrow+32)
    const int vk4  = (tid & 7) * 4;

    // q tile: transposed, pre-scaled
    for (int i = tid; i < BM * DH / 4; i += 256) {
        int row = i >> 3, k4 = (i & 7) * 4;
        float4 t4 = *reinterpret_cast<const float4*>(&qh[(size_t)(r0 + row) * DH + k4]);
        qsT[k4 + 0][row] = t4.x * SCALE_E; qsT[k4 + 1][row] = t4.y * SCALE_E;
        qsT[k4 + 2][row] = t4.z * SCALE_E; qsT[k4 + 3][row] = t4.w * SCALE_E;
    }

    // prefetch + store v tile 0 into buffer 0
    float4 pf0 = *reinterpret_cast<const float4*>(&vh[(size_t)vrow * DH + vk4]);
    float4 pf1 = *reinterpret_cast<const float4*>(&vh[(size_t)(vrow + 32) * DH + vk4]);
    *reinterpret_cast<float4*>(&vs[0][vrow][vk4]) = pf0;
    *reinterpret_cast<float4*>(&vs[0][vrow + 32][vk4]) = pf1;
    vsT[0][vk4 + 0][vrow] = pf0.x; vsT[0][vk4 + 1][vrow] = pf0.y;
    vsT[0][vk4 + 2][vrow] = pf0.z; vsT[0][vk4 + 3][vrow] = pf0.w;
    vsT[0][vk4 + 0][vrow + 32] = pf1.x; vsT[0][vk4 + 1][vrow + 32] = pf1.y;
    vsT[0][vk4 + 2][vrow + 32] = pf1.z; vsT[0][vk4 + 3][vrow + 32] = pf1.w;
    __syncthreads();

    float o[8] = {};
    float l_acc = 0.f;                   // row sum (tid&3==0 threads)
    const int orow = tid >> 2;           // 0..63
    const int od0  = (tid & 3) * 8;      // 0/8/16/24

    for (int jt = 0; jt < N_TOK / BN; jt++) {
        const int c0 = jt * BN;
        const int cur = jt & 1, nxt = cur ^ 1;

        // prefetch next v tile (global -> regs), hidden under score compute
        if (jt < N_TOK / BN - 1) {
            const float* vn = vh + (size_t)(c0 + BN) * DH;
            pf0 = *reinterpret_cast<const float4*>(&vn[(size_t)vrow * DH + vk4]);
            pf1 = *reinterpret_cast<const float4*>(&vn[(size_t)(vrow + 32) * DH + vk4]);
        }
        // prefetch this tile's 4 mask words (L2-hit latency hides under FFMA)
        unsigned wmask[4];
        {
            const int mcol = (c0 + tx * 4) >> 5;
#pragma unroll
            for (int i = 0; i < 4; i++)
                wmask[i] = g_mask[(size_t)(r0 + ty * 4 + i) * MWORDS + mcol];
        }

        // scores: s[i][j] = (q*c)[r0+ty*4+i] . v[c0+tx*4+j]
        float s[4][4] = {};
#pragma unroll
        for (int k = 0; k < DH; k++) {
            float qv[4], vv[4];
            *reinterpret_cast<float4*>(qv) =
                *reinterpret_cast<const float4*>(&qsT[k][ty * 4]);
            *reinterpret_cast<float4*>(vv) =
                *reinterpret_cast<const float4*>(&vsT[cur][k][tx * 4]);
#pragma unroll
            for (int i = 0; i < 4; i++)
#pragma unroll
                for (int j = 0; j < 4; j++) s[i][j] += qv[i] * vv[j];
        }

        // mask + exp (unnormalized); write smem ps + global attn
#pragma unroll
        for (int i = 0; i < 4; i++) {
            const int r = ty * 4 + i;
            float p[4];
#pragma unroll
            for (int j = 0; j < 4; j++) {
                int bit = (tx * 4 + j) & 31;
                p[j] = ((wmask[i] >> bit) & 1u) ? ex2f(s[i][j]) : 0.f;
            }
            *reinterpret_cast<float4*>(&ps[r][tx * 4]) =
                make_float4(p[0], p[1], p[2], p[3]);
            if (write_attn) {
                *reinterpret_cast<float4*>(
                    &attn_out[((size_t)(h * N_TOK) + r0 + r) * N_TOK + c0 + tx * 4])
                    = make_float4(p[0], p[1], p[2], p[3]);
            }
        }
        __syncthreads();   // ps ready; all reads of buffer nxt (tile jt-1) done

        // store prefetched v tile into the other buffer (overlaps o-GEMM issue)
        if (jt < N_TOK / BN - 1) {
            *reinterpret_cast<float4*>(&vs[nxt][vrow][vk4]) = pf0;
            *reinterpret_cast<float4*>(&vs[nxt][vrow + 32][vk4]) = pf1;
            vsT[nxt][vk4 + 0][vrow] = pf0.x; vsT[nxt][vk4 + 1][vrow] = pf0.y;
            vsT[nxt][vk4 + 2][vrow] = pf0.z; vsT[nxt][vk4 + 3][vrow] = pf0.w;
            vsT[nxt][vk4 + 0][vrow + 32] = pf1.x; vsT[nxt][vk4 + 1][vrow + 32] = pf1.y;
            vsT[nxt][vk4 + 2][vrow + 32] = pf1.z; vsT[nxt][vk4 + 3][vrow + 32] = pf1.w;
        }

        // o += p_tile @ v_tile; tid&3==0 threads accumulate row sum l
#pragma unroll
        for (int c4 = 0; c4 < BN; c4 += 4) {
            float a[4];
            *reinterpret_cast<float4*>(a) =
                *reinterpret_cast<const float4*>(&ps[orow][c4]);
            if ((tid & 3) == 0)
                l_acc += (a[0] + a[1]) + (a[2] + a[3]);
#pragma unroll
            for (int u = 0; u < 4; u++) {
                float vv[8];
                *reinterpret_cast<float4*>(vv) =
                    *reinterpret_cast<const float4*>(&vs[cur][c4 + u][od0]);
                *reinterpret_cast<float4*>(vv + 4) =
                    *reinterpret_cast<const float4*>(&vs[cur][c4 + u][od0 + 4]);
#pragma unroll
                for (int j = 0; j < 8; j++) o[j] += a[u] * vv[j];
            }
        }
        __syncthreads();   // o-GEMM done with ps; buffer nxt fully written
    }

    // finalize l -> 1/l
    if ((tid & 3) == 0) l_s[orow] = l_acc;
    __syncthreads();
    if (tid < BM) l_s[tid] = 1.0f / l_s[tid];
    __syncthreads();

    // o epilogue (normalized, float4 stores)
    {
        const float li = l_s[orow];
#pragma unroll
        for (int j = 0; j < 8; j++) o[j] *= li;
        float* dst = &g_otmp[(size_t)(r0 + orow) * HID + h * DH + od0];
        *reinterpret_cast<float4*>(dst)     = make_float4(o[0], o[1], o[2], o[3]);
        *reinterpret_cast<float4*>(dst + 4) = make_float4(o[4], o[5], o[6], o[7]);
    }

    // normalize own attn stripe in place (block-local; visible post-barrier)
    if (write_attn) {
        float4* base = reinterpret_cast<float4*>(
            attn_out + ((size_t)(h * N_TOK) + r0) * N_TOK);
        for (int i = tid; i < BM * (N_TOK / 4); i += 256) {
            const float li = l_s[i >> 10];          // 1024 float4 per row
            float4 v = base[i];
            v.x *= li; v.y *= li; v.z *= li; v.w *= li;
            base[i] = v;
        }
    }
}

// ---------------------------------------------------------------- shim (no-op)
// Pads the per-call launch count to 5 so ncu's fixed capture index ((5-2) mod
// L, verified on rounds 8 and 11) lands on the 444-block attention launch.
__global__ void shim_kernel() {}

// ---------------------------------------------------------------- K3: wo linear
__global__ __launch_bounds__(256) void wo_kernel(
    float* __restrict__ out,
    const float* __restrict__ wo_w, const float* __restrict__ wo_b)
{
    linear_tile(g_otmp, wo_w, wo_b, out, 2,
                (blockIdx.x >> 2) * 64, (blockIdx.x & 3) * 64, threadIdx.x);
}

// ---------------------------------------------------------------- launch
extern "C" void kernel_launch(void* const* d_in, const int* in_sizes, int n_in,
                              void* d_out, int out_size)
{
    const float* x    = (const float*)d_in[0];
    const int*   Adj  = (const int*)  d_in[1];
    const float* wq_w = (const float*)d_in[2];
    const float* wq_b = (const float*)d_in[3];
    // d_in[4], d_in[5] = wk (dead in reference: scores use V)
    const float* wv_w = (const float*)d_in[6];
    const float* wv_b = (const float*)d_in[7];
    const float* wo_w = (const float*)d_in[8];
    const float* wo_b = (const float*)d_in[9];
    float* out = (float*)d_out;

    const long long need = (long long)N_TOK * HID + (long long)HEADS * N_TOK * N_TOK;
    int write_attn = ((long long)out_size >= need) ? 1 : 0;
    float* attn_out = out + (size_t)N_TOK * HID;

    qv_pack_kernel<<<dim3(96, 4, 2), 256>>>(x, wq_w, wq_b, wv_w, wv_b, Adj);
    // 68-block runt first, then 444 blocks = exactly 3/SM x 148 (balanced wave)
    attn_kernel<<<68, 256>>>(attn_out, write_attn, 0);
    shim_kernel<<<1, 32>>>();
    attn_kernel<<<444, 256>>>(attn_out, write_attn, 68);
    wo_kernel<<<256, 256>>>(out, wo_w, wo_b);
}